// round 3
// baseline (speedup 1.0000x reference)
#include <cuda_runtime.h>
#include <mma.h>
#include <cstdint>

using namespace nvcuda;

#define Bsz 128
#define Tt  256
#define Hh  1024
#define Vv  4096
#define BHn (Bsz*Hh)

// Scratch: hidden-state history (device globals — sanctioned scratch, no allocs)
__device__ float g_h0[2][BHn];      // double-buffered layer-0 hidden state
__device__ float g_h1[Tt][BHn];     // full layer-1 hidden history (FC input), 128 MB

__device__ __forceinline__ void cp16(void* dst, const void* src){
  uint32_t d = (uint32_t)__cvta_generic_to_shared(dst);
  asm volatile("cp.async.cg.shared.global [%0], [%1], 16;" :: "r"(d), "l"(src));
}
__device__ __forceinline__ void cp_commit(){ asm volatile("cp.async.commit_group;"); }
template<int N> __device__ __forceinline__ void cp_wait(){ asm volatile("cp.async.wait_group %0;"::"n"(N)); }

// ---------------------------------------------------------------------------
// Pipelined recurrence step. Launch k (k = 0..T):
//   region0 (blocks 0..63,  if k <  T): h0[k]   = tanh(x_k*Wih0 + h0[k-1]@Whh0^T + b0)
//   region1 (blocks 64..127, if k >= 1): h1[k-1] = tanh(h0[k-1]@Wih1^T + h1[k-2]@Whh1^T + b1)
// Both regions only read state produced by launch k-1 (or earlier) -> stream order suffices.
// CTA tile: M=128 (full batch), N=16, K=1024 per GEMM. tf32 wmma, fp32 accum.
// ---------------------------------------------------------------------------
__global__ void __launch_bounds__(256) rnn_step(
  const float* __restrict__ x,
  const float* __restrict__ Wih0, const float* __restrict__ Whh0,
  const float* __restrict__ bih0, const float* __restrict__ bhh0,
  const float* __restrict__ Wih1, const float* __restrict__ Whh1,
  const float* __restrict__ bih1, const float* __restrict__ bhh1,
  int k)
{
  __shared__ __align__(16) float As[2][128][40];
  __shared__ __align__(16) float Bs[2][16][40];
  const int tid = threadIdx.x;
  const int w   = tid >> 5;
  const bool is1 = (blockIdx.x >= 64);
  if (!is1 && k == Tt) return;   // no h0[T]
  if ( is1 && k == 0 ) return;   // no h1[-1]
  const int n0 = (is1 ? (int)blockIdx.x - 64 : (int)blockIdx.x) * 16;

  wmma::fragment<wmma::accumulator,16,16,8,float> cfrag;
  wmma::fill_fragment(cfrag, 0.0f);

  const float* h0prev = g_h0[(k+1)&1];   // h0[k-1]

  auto run_gemm = [&](const float* __restrict__ A, const float* __restrict__ Wm){
    auto load = [&](int buf, int kt){
      const int k0 = kt*32;
      #pragma unroll
      for (int i=0;i<4;i++){
        int f = tid + i*256;
        int r = f >> 3, c4 = f & 7;
        cp16(&As[buf][r][c4*4], A + r*Hh + k0 + c4*4);
      }
      if (tid < 128){
        int r = tid >> 3, c4 = tid & 7;
        cp16(&Bs[buf][r][c4*4], Wm + (n0 + r)*Hh + k0 + c4*4);
      }
      cp_commit();
    };
    load(0,0); load(1,1);
    for (int kt=0; kt<32; kt++){
      if (kt==31) cp_wait<0>(); else cp_wait<1>();
      __syncthreads();
      const int buf = kt&1;
      #pragma unroll
      for (int kk=0; kk<4; kk++){
        wmma::fragment<wmma::matrix_a,16,16,8,wmma::precision::tf32,wmma::row_major> a;
        wmma::fragment<wmma::matrix_b,16,16,8,wmma::precision::tf32,wmma::col_major> b;
        wmma::load_matrix_sync(a, &As[buf][w*16][kk*8], 40);
        #pragma unroll
        for (int i=0;i<a.num_elements;i++) a.x[i] = wmma::__float_to_tf32(a.x[i]);
        wmma::load_matrix_sync(b, &Bs[buf][0][kk*8], 40);
        #pragma unroll
        for (int i=0;i<b.num_elements;i++) b.x[i] = wmma::__float_to_tf32(b.x[i]);
        wmma::mma_sync(cfrag, a, b, cfrag);
      }
      __syncthreads();
      if (kt+2 < 32) load(buf, kt+2);   // refill buffer just freed by this compute
    }
  };

  if (!is1) {
    if (k >= 1) run_gemm(h0prev, Whh0);        // k==0: pure input step
  } else {
    run_gemm(h0prev, Wih1);
    if (k >= 2) run_gemm(g_h1[k-2], Whh1);     // k==1: h1[-1] = 0
  }

  // epilogue: stage accumulator tile to smem (reuse As), add biases/input, tanh
  float* stg = &As[0][0][0];                    // needs 128*24 floats, fits
  wmma::store_matrix_sync(stg + w*16*24, cfrag, 24, wmma::mem_row_major);
  __syncthreads();

  if (!is1){
    float* dst = g_h0[k&1];
    #pragma unroll
    for (int i=0;i<8;i++){
      int f = tid + i*256;
      int r = f >> 4, cc = f & 15;
      int n = n0 + cc;
      float v = stg[r*24 + cc] + x[r*Tt + k]*Wih0[n] + bih0[n] + bhh0[n];
      dst[r*Hh + n] = tanhf(v);
    }
  } else {
    float* dst = g_h1[k-1];
    #pragma unroll
    for (int i=0;i<8;i++){
      int f = tid + i*256;
      int r = f >> 4, cc = f & 15;
      int n = n0 + cc;
      float v = stg[r*24 + cc] + bih1[n] + bhh1[n];
      dst[r*Hh + n] = tanhf(v);
    }
  }
}

// ---------------------------------------------------------------------------
// Batched FC: Out[b,t,v] = g_h1[t][b,:] @ Wfc[v,:] + bfc[v]
// Grid (V/128, T); CTA tile 128(b) x 128(v), K=1024. tf32 wmma.
// Epilogue staged through smem for coalesced float4 writes into [B,T,V].
// ---------------------------------------------------------------------------
__global__ void __launch_bounds__(256) fc_kernel(
  const float* __restrict__ Wfc, const float* __restrict__ bfc, float* __restrict__ out)
{
  __shared__ __align__(16) float smemblob[2*128*40];
  float* As  = smemblob;             // [128][40]
  float* Bss = smemblob + 128*40;    // [128][40]
  const int tid = threadIdx.x;
  const int t  = blockIdx.y;
  const int n0 = blockIdx.x * 128;
  const int w  = tid >> 5;
  const int wm = w & 3;     // warp m-block: rows wm*32..+31
  const int wn = w >> 2;    // warp n-half: cols wn*64..+63
  const float* A = g_h1[t];
  const float* Wbase = Wfc + (size_t)n0 * Hh;

  wmma::fragment<wmma::accumulator,16,16,8,float> c[2][4];
  #pragma unroll
  for (int i=0;i<2;i++)
    #pragma unroll
    for (int j=0;j<4;j++) wmma::fill_fragment(c[i][j], 0.0f);

  for (int kt=0; kt<32; kt++){
    const int k0 = kt*32;
    #pragma unroll
    for (int i=0;i<4;i++){
      int f = tid + i*256;
      int r = f>>3, c4 = f&7;
      cp16(&As [r*40 + c4*4], A     + r*Hh + k0 + c4*4);
      cp16(&Bss[r*40 + c4*4], Wbase + (size_t)r*Hh + k0 + c4*4);
    }
    cp_commit(); cp_wait<0>();
    __syncthreads();
    #pragma unroll
    for (int kk=0; kk<4; kk++){
      wmma::fragment<wmma::matrix_a,16,16,8,wmma::precision::tf32,wmma::row_major> a[2];
      #pragma unroll
      for (int i=0;i<2;i++){
        wmma::load_matrix_sync(a[i], &As[(wm*32+i*16)*40 + kk*8], 40);
        #pragma unroll
        for (int e=0;e<a[i].num_elements;e++) a[i].x[e] = wmma::__float_to_tf32(a[i].x[e]);
      }
      #pragma unroll
      for (int j=0;j<4;j++){
        wmma::fragment<wmma::matrix_b,16,16,8,wmma::precision::tf32,wmma::col_major> b;
        wmma::load_matrix_sync(b, &Bss[(wn*64 + j*16)*40 + kk*8], 40);
        #pragma unroll
        for (int e=0;e<b.num_elements;e++) b.x[e] = wmma::__float_to_tf32(b.x[e]);
        #pragma unroll
        for (int i=0;i<2;i++)
          wmma::mma_sync(c[i][j], a[i], b, c[i][j]);
      }
    }
    __syncthreads();
  }

  // Epilogue in two 128x64 halves staged through smem, bias add, float4 stores.
  float* stage = smemblob;   // [128][72] = 9216 floats < 10240 available
  #pragma unroll
  for (int h=0; h<2; h++){
    if (wn == h){
      #pragma unroll
      for (int i=0;i<2;i++)
        #pragma unroll
        for (int j=0;j<4;j++)
          wmma::store_matrix_sync(stage + (wm*32 + i*16)*72 + j*16, c[i][j], 72, wmma::mem_row_major);
    }
    __syncthreads();
    #pragma unroll
    for (int i=0;i<8;i++){
      int f = tid + i*256;
      int r = f>>4, c4 = f&15;
      int n = n0 + h*64 + c4*4;
      float4 v  = *(float4*)(stage + r*72 + c4*4);
      float4 bb = *(const float4*)(bfc + n);
      v.x += bb.x; v.y += bb.y; v.z += bb.z; v.w += bb.w;
      *(float4*)(out + (size_t)r*((size_t)Tt*Vv) + (size_t)t*Vv + n) = v;   // out[b,t,v]
    }
    __syncthreads();
  }
}

// Final hidden states -> out tail [2, B, H]
__global__ void states_kernel(float* __restrict__ out){
  size_t i = (size_t)blockIdx.x*blockDim.x + threadIdx.x;
  const size_t BTV = (size_t)Bsz*Tt*Vv;
  if (i < (size_t)BHn)            out[BTV + i] = g_h0[(Tt-1)&1][i];
  else if (i < (size_t)2*BHn)     out[BTV + i] = g_h1[Tt-1][i - BHn];
}

extern "C" void kernel_launch(void* const* d_in, const int* in_sizes, int n_in,
                              void* d_out, int out_size) {
  const float* x    = (const float*)d_in[0];
  const float* Wih0 = (const float*)d_in[1];
  const float* Whh0 = (const float*)d_in[2];
  const float* bih0 = (const float*)d_in[3];
  const float* bhh0 = (const float*)d_in[4];
  const float* Wih1 = (const float*)d_in[5];
  const float* Whh1 = (const float*)d_in[6];
  const float* bih1 = (const float*)d_in[7];
  const float* bhh1 = (const float*)d_in[8];
  const float* Wfc  = (const float*)d_in[9];
  const float* bfc  = (const float*)d_in[10];
  float* out = (float*)d_out;

  // Pipelined recurrence: launch k computes h0[k] and h1[k-1]
  for (int k = 0; k <= Tt; ++k)
    rnn_step<<<128, 256>>>(x, Wih0, Whh0, bih0, bhh0, Wih1, Whh1, bih1, bhh1, k);

  // Batched trailing linear over all (t, b)
  dim3 g(Vv/128, Tt);
  fc_kernel<<<g, 256>>>(Wfc, bfc, out);

  // Final states tail (only if harness expects the tuple's second element)
  long long need = (long long)Bsz*Tt*Vv + 2LL*BHn;
  if ((long long)out_size >= need)
    states_kernel<<<(2*BHn + 255)/256, 256>>>(out);
}